// round 1
// baseline (speedup 1.0000x reference)
#include <cuda_runtime.h>
#include <math.h>

// DUQ head: out[b,c,h,w] = exp( gamma/16 * sum_e ( (W[e,c,:] . feat[b,:,h,w]) - m[e,c]/N[c] )^2 )
// gamma = -1/(2*0.1^2) = -50  ->  scale = -50/16 = -3.125
//
// GEMM view: A = features[b] as [K=512, M=16384] (pixel-contiguous),
//            B = weights as [N=1024 (e,c), K=512] (K-contiguous).
// Block tile: 128 pixels x (8 channels x 16 e). 256 threads (8 warps).
// warp w -> channel c = blockIdx.x*8 + w; lane -> 4 contiguous pixels.
// Each thread accumulates acc[4 px][16 e] and does the full e-reduction +
// centroid subtraction + expf in registers. No cross-thread epilogue.

#define BK 16
#define BM 128
#define NC 8
#define NE 16

__global__ __launch_bounds__(256, 2)
void duq_kernel(const float* __restrict__ feat,
                const float* __restrict__ wgt,
                const float* __restrict__ mbuf,
                const float* __restrict__ Nbuf,
                float* __restrict__ out)
{
    __shared__ __align__(16) float As[BK][BM];          // 8 KB
    __shared__ __align__(16) float Bs[BK][NC][NE];      // 8 KB

    const int t    = threadIdx.x;
    const int lane = t & 31;
    const int w    = t >> 5;

    const int nb = blockIdx.x;                 // 0..7 channel group
    const int mb = blockIdx.y;                 // 0..1023 pixel tile
    const int tiles_per_batch = 16384 / BM;    // 128
    const int b  = mb / tiles_per_batch;
    const int p0 = (mb % tiles_per_batch) * BM;

    const float* A = feat + (size_t)b * 512 * 16384 + p0;   // A[f*16384 + p]
    const int c = nb * NC + w;

    float acc[4][16];
#pragma unroll
    for (int i = 0; i < 4; i++)
#pragma unroll
        for (int e = 0; e < 16; e++) acc[i][e] = 0.0f;

    for (int k0 = 0; k0 < 512; k0 += BK) {
        // ---- load A tile: BK x BM = 512 float4, 2 per thread, fully coalesced ----
#pragma unroll
        for (int i = 0; i < 2; i++) {
            int idx = t + i * 256;       // float4 index within tile
            int kk  = idx >> 5;          // 32 float4 per k-row
            int p4  = idx & 31;
            float4 v = *(const float4*)(A + (size_t)(k0 + kk) * 16384 + p4 * 4);
            *(float4*)(&As[kk][p4 * 4]) = v;
        }
        // ---- load B tile: 128 (e,c) rows x BK floats; thread -> half row ----
        {
            int r    = t >> 1;
            int half = (t & 1) * 8;
            int e    = r & 15;
            int cl   = r >> 4;
            const float* src = wgt + ((size_t)(e * 64 + nb * NC + cl)) * 512 + k0 + half;
            float4 v0 = *(const float4*)(src);
            float4 v1 = *(const float4*)(src + 4);
            Bs[half + 0][cl][e] = v0.x;
            Bs[half + 1][cl][e] = v0.y;
            Bs[half + 2][cl][e] = v0.z;
            Bs[half + 3][cl][e] = v0.w;
            Bs[half + 4][cl][e] = v1.x;
            Bs[half + 5][cl][e] = v1.y;
            Bs[half + 6][cl][e] = v1.z;
            Bs[half + 7][cl][e] = v1.w;
        }
        __syncthreads();

        // ---- compute: per k-step 1 LDS.128 (A) + 4 broadcast LDS.128 (B) + 64 FFMA ----
#pragma unroll
        for (int kk = 0; kk < BK; kk++) {
            float4 a4 = *(const float4*)(&As[kk][lane << 2]);
            float av[4] = {a4.x, a4.y, a4.z, a4.w};
            float bv[16];
#pragma unroll
            for (int q = 0; q < 4; q++) {
                float4 b4 = *(const float4*)(&Bs[kk][w][q << 2]);
                bv[4 * q + 0] = b4.x; bv[4 * q + 1] = b4.y;
                bv[4 * q + 2] = b4.z; bv[4 * q + 3] = b4.w;
            }
#pragma unroll
            for (int i = 0; i < 4; i++)
#pragma unroll
                for (int e = 0; e < 16; e++)
                    acc[i][e] = fmaf(av[i], bv[e], acc[i][e]);
        }
        __syncthreads();
    }

    // ---- epilogue: centroid subtract, e-mean of squares, RBF exp ----
    float invN = 1.0f / Nbuf[c];
    float cent[16];
#pragma unroll
    for (int e = 0; e < 16; e++) cent[e] = mbuf[e * 64 + c] * invN;

    const float scale = -3.125f;   // gamma / 16
    float res[4];
#pragma unroll
    for (int i = 0; i < 4; i++) {
        float s = 0.0f;
#pragma unroll
        for (int e = 0; e < 16; e++) {
            float d = acc[i][e] - cent[e];
            s = fmaf(d, d, s);
        }
        res[i] = expf(s * scale);
    }

    float* o = out + ((size_t)b * 64 + c) * 16384 + p0 + (lane << 2);
    *(float4*)o = make_float4(res[0], res[1], res[2], res[3]);
}

extern "C" void kernel_launch(void* const* d_in, const int* in_sizes, int n_in,
                              void* d_out, int out_size)
{
    const float* feat = (const float*)d_in[0];   // [8, 512, 128, 128]
    const float* wgt  = (const float*)d_in[1];   // [16, 64, 512]
    const float* m    = (const float*)d_in[2];   // [16, 64]
    const float* N    = (const float*)d_in[3];   // [64]
    float* out        = (float*)d_out;           // [8, 64, 128, 128]

    dim3 grid(8, 1024);   // x = channel groups (shares A tile across x -> L2 reuse)
    dim3 block(256);
    duq_kernel<<<grid, block>>>(feat, wgt, m, N, out);
}